// round 5
// baseline (speedup 1.0000x reference)
#include <cuda_runtime.h>
#include <cstdint>

// LinearAttention n=4, L=8192, h=8, d=m=64 — mma.sync tf32, single-sync pipelines.
// out[pair,l,m] = z_l * sum_d phiQ[l,d] * KV[d,m]
// KV[d,m] = sum_s phiK[s,d] V[s,m];  z_l = 1/(phiQ[l,:]·ksum + 1e-6)

#define NB 4
#define LL 8192
#define NH 8
#define DD 64
#define NPAIR 32
#define SPL 32
#define CHUNK (LL / SPL)       // 256
#define ROWS 32                // s rows per smem round
#define NRND (CHUNK / ROWS)    // 8
#define PADA 68                // gid-major-row access pattern (out qs)
#define PADB 72                // tig-major-row access pattern (Ks/Vs/kvs)
#define TLQ 128

__device__ float g_kv_part[SPL * NPAIR * DD * DD];   // 16 MB
__device__ float g_ksum_part[SPL * NPAIR * DD];
__device__ float g_kv[NPAIR * DD * DD];              // tf32-rounded
__device__ float g_ksum[NPAIR * DD];                 // fp32

// ---------------- helpers ----------------
__device__ __forceinline__ uint32_t s2u(const void* p) {
    uint32_t a;
    asm("{ .reg .u64 t; cvta.to.shared.u64 t, %1; cvt.u32.u64 %0, t; }" : "=r"(a) : "l"(p));
    return a;
}
__device__ __forceinline__ uint32_t totf(float f) {
    uint32_t r; asm("cvt.rna.tf32.f32 %0, %1;" : "=r"(r) : "f"(f)); return r;
}
__device__ __forceinline__ float phi(float x) {
    x *= 0.35355339059327378f;            // 64^-0.25
    return x > 0.f ? x + 1.f : __expf(x);
}
__device__ __forceinline__ void mma8(float c[4], uint32_t a0, uint32_t a1,
                                     uint32_t a2, uint32_t a3,
                                     uint32_t b0, uint32_t b1) {
    asm volatile(
        "mma.sync.aligned.m16n8k8.row.col.f32.tf32.tf32.f32 "
        "{%0,%1,%2,%3}, {%4,%5,%6,%7}, {%8,%9}, {%0,%1,%2,%3};"
        : "+f"(c[0]), "+f"(c[1]), "+f"(c[2]), "+f"(c[3])
        : "r"(a0), "r"(a1), "r"(a2), "r"(a3), "r"(b0), "r"(b1));
}
__device__ __forceinline__ void cp16(uint32_t dst, const void* src) {
    asm volatile("cp.async.cg.shared.global [%0], [%1], 16;"
                 :: "r"(dst), "l"(src) : "memory");
}
#define CP_COMMIT() asm volatile("cp.async.commit_group;" ::: "memory")
#define CP_WAIT(N)  asm volatile("cp.async.wait_group %0;" :: "n"(N) : "memory")

// ---------------- kernel 1: KV partials ----------------
__global__ __launch_bounds__(256)
void kv_kernel(const float* __restrict__ K, const float* __restrict__ V) {
    __shared__ float Ks[2][ROWS][PADB];   // tf32 phi(K), double-buffered
    __shared__ float Vs[3][ROWS][PADB];   // raw fp32 V, triple-buffered
    __shared__ float ksum_s[DD];

    const int tid = threadIdx.x, warp = tid >> 5, lane = tid & 31;
    const int gid = lane >> 2, tig = lane & 3;
    const int pair = blockIdx.y, b = pair >> 3, hh = pair & 7;
    const int split = blockIdx.x;
    const int wd = warp & 3, wm = warp >> 2;
    const int d0 = wd * 16, m0 = wm * 32;

    const size_t rstr = (size_t)NH * DD;
    const int lrow = tid >> 3, lcol = (tid & 7) * 8;
    const float* Kp = K + ((size_t)b * LL + split * CHUNK + lrow) * rstr + hh * DD + lcol;
    const float* Vp = V + ((size_t)b * LL + split * CHUNK + lrow) * rstr + hh * DD + lcol;
    uint32_t vdst[3];
    vdst[0] = s2u(&Vs[0][lrow][lcol]);
    vdst[1] = s2u(&Vs[1][lrow][lcol]);
    vdst[2] = s2u(&Vs[2][lrow][lcol]);

    if (tid < DD) ksum_s[tid] = 0.f;

    float acc[4][4];
    #pragma unroll
    for (int i = 0; i < 4; i++)
        #pragma unroll
        for (int j = 0; j < 4; j++) acc[i][j] = 0.f;
    float ks[8];
    #pragma unroll
    for (int j = 0; j < 8; j++) ks[j] = 0.f;

    // prologue: V(0) via cp.async, K(0) via LDG
    cp16(vdst[0], Vp); cp16(vdst[0] + 16, Vp + 4);
    CP_COMMIT();
    float4 ka = *(const float4*)Kp;
    float4 kb = *(const float4*)(Kp + 4);

    #pragma unroll
    for (int r = 0; r < NRND; r++) {
        // issue V(r+1)
        if (r + 1 < NRND) {
            const size_t go = (size_t)(r + 1) * ROWS * rstr;
            const uint32_t vd = vdst[(r + 1) % 3];
            cp16(vd, Vp + go); cp16(vd + 16, Vp + go + 4);
            CP_COMMIT();
        }
        // stage K(r): phi + ksum + tf32, once per element
        {
            float p[8];
            p[0] = phi(ka.x); p[1] = phi(ka.y); p[2] = phi(ka.z); p[3] = phi(ka.w);
            p[4] = phi(kb.x); p[5] = phi(kb.y); p[6] = phi(kb.z); p[7] = phi(kb.w);
            #pragma unroll
            for (int j = 0; j < 8; j++) ks[j] += p[j];
            uint4 u0, u1;
            u0.x = totf(p[0]); u0.y = totf(p[1]); u0.z = totf(p[2]); u0.w = totf(p[3]);
            u1.x = totf(p[4]); u1.y = totf(p[5]); u1.z = totf(p[6]); u1.w = totf(p[7]);
            *(uint4*)&Ks[r & 1][lrow][lcol]     = u0;
            *(uint4*)&Ks[r & 1][lrow][lcol + 4] = u1;
        }
        // prefetch K(r+1)
        if (r + 1 < NRND) {
            const size_t go = (size_t)(r + 1) * ROWS * rstr;
            ka = *(const float4*)(Kp + go);
            kb = *(const float4*)(Kp + go + 4);
            CP_WAIT(1);     // V(r) landed
        } else {
            CP_WAIT(0);
        }
        __syncthreads();    // single barrier: Ks(r) visible, V(r) landed, MMA(r-1) drained

        const int vb = r % 3, kbuf = r & 1;
        #pragma unroll
        for (int kstp = 0; kstp < 4; kstp++) {
            const int sb = kstp * 8;
            const uint32_t a0 = __float_as_uint(Ks[kbuf][sb + tig][d0 + gid]);
            const uint32_t a1 = __float_as_uint(Ks[kbuf][sb + tig][d0 + gid + 8]);
            const uint32_t a2 = __float_as_uint(Ks[kbuf][sb + tig + 4][d0 + gid]);
            const uint32_t a3 = __float_as_uint(Ks[kbuf][sb + tig + 4][d0 + gid + 8]);
            #pragma unroll
            for (int nt = 0; nt < 4; nt++) {
                const int m = m0 + nt * 8 + gid;
                const uint32_t b0 = __float_as_uint(Vs[vb][sb + tig][m]);
                const uint32_t b1 = __float_as_uint(Vs[vb][sb + tig + 4][m]);
                mma8(acc[nt], a0, a1, a2, a3, b0, b1);
            }
        }
    }

    // epilogue
    float* dst = g_kv_part + ((size_t)split * NPAIR + pair) * DD * DD;
    const int dlo = d0 + gid;
    #pragma unroll
    for (int nt = 0; nt < 4; nt++) {
        const int m = m0 + nt * 8 + 2 * tig;
        *(float2*)(dst + dlo * DD + m)       = make_float2(acc[nt][0], acc[nt][1]);
        *(float2*)(dst + (dlo + 8) * DD + m) = make_float2(acc[nt][2], acc[nt][3]);
    }
    #pragma unroll
    for (int j = 0; j < 8; j++) {
        ks[j] += __shfl_xor_sync(0xffffffffu, ks[j], 8);
        ks[j] += __shfl_xor_sync(0xffffffffu, ks[j], 16);
    }
    if (lane < 8) {
        #pragma unroll
        for (int j = 0; j < 8; j++)
            atomicAdd(&ksum_s[lane * 8 + j], ks[j]);
    }
    __syncthreads();
    if (tid < DD)
        g_ksum_part[((size_t)split * NPAIR + pair) * DD + tid] = ksum_s[tid];
}

// ---------------- reduce partials (KV -> tf32, ksum -> fp32) ----------------
__global__ void reduce_kernel() {
    const int i = blockIdx.x * blockDim.x + threadIdx.x;
    if (i < NPAIR * DD * DD) {
        float s = 0.f;
        #pragma unroll
        for (int p = 0; p < SPL; p++) s += g_kv_part[(size_t)p * NPAIR * DD * DD + i];
        g_kv[i] = __uint_as_float(totf(s));
    } else {
        const int j = i - NPAIR * DD * DD;
        if (j < NPAIR * DD) {
            float s = 0.f;
            #pragma unroll
            for (int p = 0; p < SPL; p++) s += g_ksum_part[p * NPAIR * DD + j];
            g_ksum[j] = s;
        }
    }
}

// ---------------- kernel 2: output GEMM ----------------
// dynamic smem: qs[128][PADA] + kvs[64][PADB]
#define K2_SMEM ((TLQ * PADA + DD * PADB) * 4)

__global__ __launch_bounds__(256)
void out_kernel(const float* __restrict__ Q, float* __restrict__ O) {
    extern __shared__ float sm2[];
    float (*qs)[PADA]  = (float(*)[PADA])sm2;
    float (*kvs)[PADB] = (float(*)[PADB])(sm2 + TLQ * PADA);

    const int tid = threadIdx.x, warp = tid >> 5, lane = tid & 31;
    const int gid = lane >> 2, tig = lane & 3;
    const int pair = blockIdx.y, b = pair >> 3, hh = pair & 7;
    const int l0 = blockIdx.x * TLQ;

    // KV tile via cp.async (overlaps q-prep below)
    {
        const float* kvp = g_kv + (size_t)pair * DD * DD;
        #pragma unroll
        for (int k = 0; k < 4; k++) {
            const int f = (k * 256 + tid) * 4;
            cp16(s2u(&kvs[f >> 6][f & 63]), kvp + f);
        }
        CP_COMMIT();
    }

    // q prep: 2 threads per row; ksum by LDG broadcast (L1-resident)
    {
        const int l = tid >> 1, half = tid & 1;
        const float* qrow = Q + ((size_t)b * LL + l0 + l) * (NH * DD)
                              + (size_t)hh * DD + half * 32;
        const float* ksg = g_ksum + pair * DD + half * 32;
        float4 qv[8];
        float accz = 0.f;
        #pragma unroll
        for (int i = 0; i < 8; i++) {
            float4 q4 = *(const float4*)(qrow + i * 4);
            float4 k4 = *(const float4*)(ksg + i * 4);
            q4.x = phi(q4.x); q4.y = phi(q4.y); q4.z = phi(q4.z); q4.w = phi(q4.w);
            accz += q4.x * k4.x + q4.y * k4.y + q4.z * k4.z + q4.w * k4.w;
            qv[i] = q4;
        }
        accz += __shfl_xor_sync(0xffffffffu, accz, 1);
        const float z = 1.f / (accz + 1e-6f);
        #pragma unroll
        for (int i = 0; i < 8; i++) {
            uint4 u;
            u.x = totf(qv[i].x * z); u.y = totf(qv[i].y * z);
            u.z = totf(qv[i].z * z); u.w = totf(qv[i].w * z);
            *(uint4*)&qs[l][half * 32 + i * 4] = u;
        }
    }
    CP_WAIT(0);
    __syncthreads();

    // 32l x 32m per warp
    const int l0w = (warp & 3) * 32;
    const int m0  = (warp >> 2) * 32;
    float acc[2][4][4];
    #pragma unroll
    for (int lt = 0; lt < 2; lt++)
        #pragma unroll
        for (int i = 0; i < 4; i++)
            #pragma unroll
            for (int j = 0; j < 4; j++) acc[lt][i][j] = 0.f;

    #pragma unroll
    for (int kk = 0; kk < 8; kk++) {
        const int k0 = kk * 8;
        uint32_t a[2][4];
        #pragma unroll
        for (int lt = 0; lt < 2; lt++) {
            const int row = l0w + lt * 16;
            a[lt][0] = __float_as_uint(qs[row + gid][k0 + tig]);
            a[lt][1] = __float_as_uint(qs[row + gid + 8][k0 + tig]);
            a[lt][2] = __float_as_uint(qs[row + gid][k0 + tig + 4]);
            a[lt][3] = __float_as_uint(qs[row + gid + 8][k0 + tig + 4]);
        }
        #pragma unroll
        for (int nt = 0; nt < 4; nt++) {
            const int m = m0 + nt * 8 + gid;
            const uint32_t b0 = __float_as_uint(kvs[k0 + tig][m]);
            const uint32_t b1 = __float_as_uint(kvs[k0 + tig + 4][m]);
            mma8(acc[0][nt], a[0][0], a[0][1], a[0][2], a[0][3], b0, b1);
            mma8(acc[1][nt], a[1][0], a[1][1], a[1][2], a[1][3], b0, b1);
        }
    }

    #pragma unroll
    for (int lt = 0; lt < 2; lt++) {
        float* dst = O + ((size_t)pair * LL + l0 + l0w + lt * 16 + gid) * DD;
        #pragma unroll
        for (int nt = 0; nt < 4; nt++) {
            const int m = m0 + nt * 8 + 2 * tig;
            *(float2*)(dst + m)          = make_float2(acc[lt][nt][0], acc[lt][nt][1]);
            *(float2*)(dst + 8 * DD + m) = make_float2(acc[lt][nt][2], acc[lt][nt][3]);
        }
    }
}

// ---------------- launch ----------------
extern "C" void kernel_launch(void* const* d_in, const int* in_sizes, int n_in,
                              void* d_out, int out_size) {
    const float* Q = (const float*)d_in[0];
    const float* K = (const float*)d_in[1];
    const float* V = (const float*)d_in[2];
    float* O = (float*)d_out;

    cudaFuncSetAttribute(out_kernel, cudaFuncAttributeMaxDynamicSharedMemorySize, K2_SMEM);

    kv_kernel<<<dim3(SPL, NPAIR), 256>>>(K, V);
    reduce_kernel<<<(NPAIR * DD * DD + NPAIR * DD + 255) / 256, 256>>>();
    out_kernel<<<dim3(LL / TLQ, NPAIR), 256, K2_SMEM>>>(Q, O);
}

// round 6
// speedup vs baseline: 1.0919x; 1.0919x over previous
#include <cuda_runtime.h>
#include <cstdint>

// LinearAttention n=4, L=8192, h=8, d=m=64 — mma.sync tf32.
// out[pair,l,m] = z_l * sum_d phiQ[l,d] * KV[d,m]
// KV[d,m] = sum_s phiK[s,d] V[s,m];  z_l = 1/(phiQ[l,:]·ksum + 1e-6)

#define NB 4
#define LL 8192
#define NH 8
#define DD 64
#define NPAIR 32
#define SPL 32
#define CHUNK (LL / SPL)       // 256
#define ROWS 32                // s rows per smem round
#define NRND (CHUNK / ROWS)    // 8
#define PADA 68                // gid-major-row access pattern (out qs)
#define PADB 72                // tig-major-row access pattern (Ks/Vs/kvs)
#define TLQ 64                 // out l-tile

__device__ float g_kv_part[SPL * NPAIR * DD * DD];   // 16 MB
__device__ float g_ksum_part[SPL * NPAIR * DD];
__device__ float g_kv[NPAIR * DD * DD];              // tf32-rounded
__device__ float g_ksum[NPAIR * DD];                 // fp32

// ---------------- helpers ----------------
__device__ __forceinline__ uint32_t s2u(const void* p) {
    uint32_t a;
    asm("{ .reg .u64 t; cvta.to.shared.u64 t, %1; cvt.u32.u64 %0, t; }" : "=r"(a) : "l"(p));
    return a;
}
__device__ __forceinline__ uint32_t totf(float f) {
    uint32_t r; asm("cvt.rna.tf32.f32 %0, %1;" : "=r"(r) : "f"(f)); return r;
}
__device__ __forceinline__ float phi(float x) {
    x *= 0.35355339059327378f;            // 64^-0.25
    return x > 0.f ? x + 1.f : __expf(x);
}
__device__ __forceinline__ void mma8(float c[4], uint32_t a0, uint32_t a1,
                                     uint32_t a2, uint32_t a3,
                                     uint32_t b0, uint32_t b1) {
    asm volatile(
        "mma.sync.aligned.m16n8k8.row.col.f32.tf32.tf32.f32 "
        "{%0,%1,%2,%3}, {%4,%5,%6,%7}, {%8,%9}, {%0,%1,%2,%3};"
        : "+f"(c[0]), "+f"(c[1]), "+f"(c[2]), "+f"(c[3])
        : "r"(a0), "r"(a1), "r"(a2), "r"(a3), "r"(b0), "r"(b1));
}
__device__ __forceinline__ void cp16(uint32_t dst, const void* src) {
    asm volatile("cp.async.cg.shared.global [%0], [%1], 16;"
                 :: "r"(dst), "l"(src) : "memory");
}
#define CP_COMMIT() asm volatile("cp.async.commit_group;" ::: "memory")
#define CP_WAIT(N)  asm volatile("cp.async.wait_group %0;" :: "n"(N) : "memory")

// ---------------- kernel 1: KV partials (R4-proven version) ----------------
__global__ __launch_bounds__(256)
void kv_kernel(const float* __restrict__ K, const float* __restrict__ V) {
    __shared__ float Ks[ROWS][PADB];      // tf32-converted phi(K)
    __shared__ float Vs[2][ROWS][PADB];   // raw fp32 V (fed as tf32 bits)
    __shared__ float ksum_s[DD];

    const int tid = threadIdx.x, warp = tid >> 5, lane = tid & 31;
    const int gid = lane >> 2, tig = lane & 3;
    const int pair = blockIdx.y, b = pair >> 3, hh = pair & 7;
    const int split = blockIdx.x;
    const int wd = warp & 3, wm = warp >> 2;
    const int d0 = wd * 16, m0 = wm * 32;

    const size_t rstr = (size_t)NH * DD;
    const int lrow = tid >> 3, lcol = (tid & 7) * 8;
    const float* Kp = K + ((size_t)b * LL + split * CHUNK + lrow) * rstr + hh * DD + lcol;
    const float* Vp = V + ((size_t)b * LL + split * CHUNK + lrow) * rstr + hh * DD + lcol;
    const uint32_t vdst = s2u(&Vs[0][lrow][lcol]);
    const uint32_t bufB = ROWS * PADB * 4;

    if (tid < DD) ksum_s[tid] = 0.f;

    float acc[4][4];
    #pragma unroll
    for (int i = 0; i < 4; i++)
        #pragma unroll
        for (int j = 0; j < 4; j++) acc[i][j] = 0.f;
    float ks[8];
    #pragma unroll
    for (int j = 0; j < 8; j++) ks[j] = 0.f;

    cp16(vdst, Vp); cp16(vdst + 16, Vp + 4);
    CP_COMMIT();
    float4 ka = *(const float4*)Kp;
    float4 kb = *(const float4*)(Kp + 4);

    #pragma unroll
    for (int r = 0; r < NRND; r++) {
        if (r + 1 < NRND) {
            const size_t go = (size_t)(r + 1) * ROWS * rstr;
            const uint32_t so = ((r + 1) & 1) * bufB;
            cp16(vdst + so, Vp + go); cp16(vdst + so + 16, Vp + go + 4);
            CP_COMMIT();
        }
        {
            float p[8];
            p[0] = phi(ka.x); p[1] = phi(ka.y); p[2] = phi(ka.z); p[3] = phi(ka.w);
            p[4] = phi(kb.x); p[5] = phi(kb.y); p[6] = phi(kb.z); p[7] = phi(kb.w);
            #pragma unroll
            for (int j = 0; j < 8; j++) ks[j] += p[j];
            uint4 u0, u1;
            u0.x = totf(p[0]); u0.y = totf(p[1]); u0.z = totf(p[2]); u0.w = totf(p[3]);
            u1.x = totf(p[4]); u1.y = totf(p[5]); u1.z = totf(p[6]); u1.w = totf(p[7]);
            *(uint4*)&Ks[lrow][lcol]     = u0;
            *(uint4*)&Ks[lrow][lcol + 4] = u1;
        }
        if (r + 1 < NRND) {
            const size_t go = (size_t)(r + 1) * ROWS * rstr;
            ka = *(const float4*)(Kp + go);
            kb = *(const float4*)(Kp + go + 4);
            CP_WAIT(1);
        } else {
            CP_WAIT(0);
        }
        __syncthreads();

        const int buf = r & 1;
        #pragma unroll
        for (int kstp = 0; kstp < 4; kstp++) {
            const int sb = kstp * 8;
            const uint32_t a0 = __float_as_uint(Ks[sb + tig][d0 + gid]);
            const uint32_t a1 = __float_as_uint(Ks[sb + tig][d0 + gid + 8]);
            const uint32_t a2 = __float_as_uint(Ks[sb + tig + 4][d0 + gid]);
            const uint32_t a3 = __float_as_uint(Ks[sb + tig + 4][d0 + gid + 8]);
            #pragma unroll
            for (int nt = 0; nt < 4; nt++) {
                const int m = m0 + nt * 8 + gid;
                const uint32_t b0 = __float_as_uint(Vs[buf][sb + tig][m]);
                const uint32_t b1 = __float_as_uint(Vs[buf][sb + tig + 4][m]);
                mma8(acc[nt], a0, a1, a2, a3, b0, b1);
            }
        }
        __syncthreads();
    }

    float* dst = g_kv_part + ((size_t)split * NPAIR + pair) * DD * DD;
    const int dlo = d0 + gid;
    #pragma unroll
    for (int nt = 0; nt < 4; nt++) {
        const int m = m0 + nt * 8 + 2 * tig;
        *(float2*)(dst + dlo * DD + m)       = make_float2(acc[nt][0], acc[nt][1]);
        *(float2*)(dst + (dlo + 8) * DD + m) = make_float2(acc[nt][2], acc[nt][3]);
    }
    #pragma unroll
    for (int j = 0; j < 8; j++) {
        ks[j] += __shfl_xor_sync(0xffffffffu, ks[j], 8);
        ks[j] += __shfl_xor_sync(0xffffffffu, ks[j], 16);
    }
    if (lane < 8) {
        #pragma unroll
        for (int j = 0; j < 8; j++)
            atomicAdd(&ksum_s[lane * 8 + j], ks[j]);
    }
    __syncthreads();
    if (tid < DD)
        g_ksum_part[((size_t)split * NPAIR + pair) * DD + tid] = ksum_s[tid];
}

// ---------------- reduce partials ----------------
__global__ void reduce_kernel() {
    const int i = blockIdx.x * blockDim.x + threadIdx.x;
    if (i < NPAIR * DD * DD) {
        float s = 0.f;
        #pragma unroll
        for (int p = 0; p < SPL; p++) s += g_kv_part[(size_t)p * NPAIR * DD * DD + i];
        g_kv[i] = __uint_as_float(totf(s));
    } else {
        const int j = i - NPAIR * DD * DD;
        if (j < NPAIR * DD) {
            float s = 0.f;
            #pragma unroll
            for (int p = 0; p < SPL; p++) s += g_ksum_part[p * NPAIR * DD + j];
            g_ksum[j] = s;
        }
    }
}

// ---------------- kernel 2: output GEMM (64-l tile, z at epilogue) ----------------
// dynamic smem: qs[64][PADA] + kvs[64][PADB] + zs[64]
#define K2_SMEM ((TLQ * PADA + DD * PADB + TLQ) * 4)

__global__ __launch_bounds__(256, 6)
void out_kernel(const float* __restrict__ Q, float* __restrict__ O, int xoff) {
    extern __shared__ float sm2[];
    float (*qs)[PADA]  = (float(*)[PADA])sm2;
    float (*kvs)[PADB] = (float(*)[PADB])(sm2 + TLQ * PADA);
    float* zs = sm2 + TLQ * PADA + DD * PADB;

    const int tid = threadIdx.x, warp = tid >> 5, lane = tid & 31;
    const int gid = lane >> 2, tig = lane & 3;
    const int pair = blockIdx.y, b = pair >> 3, hh = pair & 7;
    const int l0 = (blockIdx.x + xoff) * TLQ;

    // KV tile via cp.async (overlaps q-prep)
    {
        const float* kvp = g_kv + (size_t)pair * DD * DD;
        #pragma unroll
        for (int k = 0; k < 4; k++) {
            const int f = (k * 256 + tid) * 4;
            cp16(s2u(&kvs[f >> 6][f & 63]), kvp + f);
        }
        CP_COMMIT();
    }

    // q prep: 4 threads per row (16 d each); phi -> tf32 STS immediately;
    // z computed in fp32, applied at epilogue.
    {
        const int row = tid >> 2, qtr = tid & 3;
        const float* qrow = Q + ((size_t)b * LL + l0 + row) * (NH * DD)
                              + (size_t)hh * DD + qtr * 16;
        const float* ksg = g_ksum + pair * DD + qtr * 16;
        float accz = 0.f;
        #pragma unroll
        for (int i = 0; i < 4; i++) {
            float4 q4 = *(const float4*)(qrow + i * 4);
            float4 k4 = __ldg((const float4*)(ksg + i * 4));
            q4.x = phi(q4.x); q4.y = phi(q4.y); q4.z = phi(q4.z); q4.w = phi(q4.w);
            accz += q4.x * k4.x + q4.y * k4.y + q4.z * k4.z + q4.w * k4.w;
            uint4 u;
            u.x = totf(q4.x); u.y = totf(q4.y); u.z = totf(q4.z); u.w = totf(q4.w);
            *(uint4*)&qs[row][qtr * 16 + i * 4] = u;
        }
        accz += __shfl_xor_sync(0xffffffffu, accz, 1);
        accz += __shfl_xor_sync(0xffffffffu, accz, 2);
        if (qtr == 0) zs[row] = 1.f / (accz + 1e-6f);
    }
    CP_WAIT(0);
    __syncthreads();

    // 16l x 32m per warp
    const int lw = (warp & 3) * 16;
    const int m0 = (warp >> 2) * 32;
    float acc[4][4];
    #pragma unroll
    for (int i = 0; i < 4; i++)
        #pragma unroll
        for (int j = 0; j < 4; j++) acc[i][j] = 0.f;

    #pragma unroll
    for (int kk = 0; kk < 8; kk++) {
        const int k0 = kk * 8;
        const uint32_t a0 = __float_as_uint(qs[lw + gid][k0 + tig]);
        const uint32_t a1 = __float_as_uint(qs[lw + gid + 8][k0 + tig]);
        const uint32_t a2 = __float_as_uint(qs[lw + gid][k0 + tig + 4]);
        const uint32_t a3 = __float_as_uint(qs[lw + gid + 8][k0 + tig + 4]);
        #pragma unroll
        for (int nt = 0; nt < 4; nt++) {
            const int m = m0 + nt * 8 + gid;
            const uint32_t b0 = __float_as_uint(kvs[k0 + tig][m]);
            const uint32_t b1 = __float_as_uint(kvs[k0 + tig + 4][m]);
            mma8(acc[nt], a0, a1, a2, a3, b0, b1);
        }
    }

    const float z0 = zs[lw + gid];
    const float z1 = zs[lw + gid + 8];
    float* dst = O + ((size_t)pair * LL + l0 + lw + gid) * DD;
    #pragma unroll
    for (int nt = 0; nt < 4; nt++) {
        const int m = m0 + nt * 8 + 2 * tig;
        *(float2*)(dst + m)          = make_float2(acc[nt][0] * z0, acc[nt][1] * z0);
        *(float2*)(dst + 8 * DD + m) = make_float2(acc[nt][2] * z1, acc[nt][3] * z1);
    }
}

// ---------------- launch ----------------
extern "C" void kernel_launch(void* const* d_in, const int* in_sizes, int n_in,
                              void* d_out, int out_size) {
    const float* Q = (const float*)d_in[0];
    const float* K = (const float*)d_in[1];
    const float* V = (const float*)d_in[2];
    float* O = (float*)d_out;

    cudaFuncSetAttribute(out_kernel, cudaFuncAttributeMaxDynamicSharedMemorySize, K2_SMEM);

    const int XT = LL / TLQ;   // 128 x-tiles
    kv_kernel<<<dim3(SPL, NPAIR), 256>>>(K, V);
    reduce_kernel<<<(NPAIR * DD * DD + NPAIR * DD + 255) / 256, 256>>>();
    out_kernel<<<dim3(XT / 2, NPAIR), 256, K2_SMEM>>>(Q, O, 0);        // launch pos 3 (mod 4)
    out_kernel<<<dim3(XT / 2, NPAIR), 256, K2_SMEM>>>(Q, O, XT / 2);   // launch pos 0 (mod 4)
}

// round 8
// speedup vs baseline: 1.1218x; 1.0274x over previous
#include <cuda_runtime.h>
#include <cstdint>

// LinearAttention n=4, L=8192, h=8, d=m=64 — mma.sync tf32.
// out[pair,l,m] = z_l * sum_d phiQ[l,d] * KV[d,m]
// KV[d,m] = sum_s phiK[s,d] V[s,m];  z_l = 1/(phiQ[l,:]·ksum + 1e-6)

#define NB 4
#define LL 8192
#define NH 8
#define DD 64
#define NPAIR 32
#define SPL 32
#define CHUNK (LL / SPL)       // 256
#define ROWS 32                // s rows per smem round
#define PADA 68                // qs row width: 64 data + 4 (gid-major conflict-free)
#define PADB 72                // Ks/Vs/kvs row width: 64 data + 8 (tig-major conflict-free)
#define NRND (CHUNK / ROWS)    // 8
#define TLQ 64                 // out l-tile rows
#define NT  4                  // l-tiles per out CTA

__device__ float g_kv_part[SPL * NPAIR * DD * DD];   // 16 MB
__device__ float g_ksum_part[SPL * NPAIR * DD];
__device__ float g_kv[NPAIR * DD * DD];              // tf32-rounded
__device__ float g_ksum[NPAIR * DD];                 // fp32

// ---------------- helpers ----------------
__device__ __forceinline__ uint32_t s2u(const void* p) {
    uint32_t a;
    asm("{ .reg .u64 t; cvta.to.shared.u64 t, %1; cvt.u32.u64 %0, t; }" : "=r"(a) : "l"(p));
    return a;
}
__device__ __forceinline__ uint32_t totf(float f) {
    uint32_t r; asm("cvt.rna.tf32.f32 %0, %1;" : "=r"(r) : "f"(f)); return r;
}
__device__ __forceinline__ float phi(float x) {
    x *= 0.35355339059327378f;            // 64^-0.25
    return x > 0.f ? x + 1.f : __expf(x);
}
__device__ __forceinline__ void mma8(float c[4], uint32_t a0, uint32_t a1,
                                     uint32_t a2, uint32_t a3,
                                     uint32_t b0, uint32_t b1) {
    asm volatile(
        "mma.sync.aligned.m16n8k8.row.col.f32.tf32.tf32.f32 "
        "{%0,%1,%2,%3}, {%4,%5,%6,%7}, {%8,%9}, {%0,%1,%2,%3};"
        : "+f"(c[0]), "+f"(c[1]), "+f"(c[2]), "+f"(c[3])
        : "r"(a0), "r"(a1), "r"(a2), "r"(a3), "r"(b0), "r"(b1));
}
__device__ __forceinline__ void cp16(uint32_t dst, const void* src) {
    asm volatile("cp.async.cg.shared.global [%0], [%1], 16;"
                 :: "r"(dst), "l"(src) : "memory");
}
#define CP_COMMIT() asm volatile("cp.async.commit_group;" ::: "memory")
#define CP_WAIT(N)  asm volatile("cp.async.wait_group %0;" :: "n"(N) : "memory")

// ---------------- kernel 1: KV partials (R4/R6-proven) ----------------
__global__ __launch_bounds__(256)
void kv_kernel(const float* __restrict__ K, const float* __restrict__ V) {
    __shared__ float Ks[ROWS][PADB];      // tf32-converted phi(K)
    __shared__ float Vs[2][ROWS][PADB];   // raw fp32 V (fed as tf32 bits)
    __shared__ float ksum_s[DD];

    const int tid = threadIdx.x, warp = tid >> 5, lane = tid & 31;
    const int gid = lane >> 2, tig = lane & 3;
    const int pair = blockIdx.y, b = pair >> 3, hh = pair & 7;
    const int split = blockIdx.x;
    const int wd = warp & 3, wm = warp >> 2;
    const int d0 = wd * 16, m0 = wm * 32;

    const size_t rstr = (size_t)NH * DD;
    const int lrow = tid >> 3, lcol = (tid & 7) * 8;
    const float* Kp = K + ((size_t)b * LL + split * CHUNK + lrow) * rstr + hh * DD + lcol;
    const float* Vp = V + ((size_t)b * LL + split * CHUNK + lrow) * rstr + hh * DD + lcol;
    const uint32_t vdst = s2u(&Vs[0][lrow][lcol]);
    const uint32_t bufB = ROWS * PADB * 4;

    if (tid < DD) ksum_s[tid] = 0.f;

    float acc[4][4];
    #pragma unroll
    for (int i = 0; i < 4; i++)
        #pragma unroll
        for (int j = 0; j < 4; j++) acc[i][j] = 0.f;
    float ks[8];
    #pragma unroll
    for (int j = 0; j < 8; j++) ks[j] = 0.f;

    cp16(vdst, Vp); cp16(vdst + 16, Vp + 4);
    CP_COMMIT();
    float4 ka = *(const float4*)Kp;
    float4 kb = *(const float4*)(Kp + 4);

    #pragma unroll
    for (int r = 0; r < NRND; r++) {
        if (r + 1 < NRND) {
            const size_t go = (size_t)(r + 1) * ROWS * rstr;
            const uint32_t so = ((r + 1) & 1) * bufB;
            cp16(vdst + so, Vp + go); cp16(vdst + so + 16, Vp + go + 4);
            CP_COMMIT();
        }
        {
            float p[8];
            p[0] = phi(ka.x); p[1] = phi(ka.y); p[2] = phi(ka.z); p[3] = phi(ka.w);
            p[4] = phi(kb.x); p[5] = phi(kb.y); p[6] = phi(kb.z); p[7] = phi(kb.w);
            #pragma unroll
            for (int j = 0; j < 8; j++) ks[j] += p[j];
            uint4 u0, u1;
            u0.x = totf(p[0]); u0.y = totf(p[1]); u0.z = totf(p[2]); u0.w = totf(p[3]);
            u1.x = totf(p[4]); u1.y = totf(p[5]); u1.z = totf(p[6]); u1.w = totf(p[7]);
            *(uint4*)&Ks[lrow][lcol]     = u0;
            *(uint4*)&Ks[lrow][lcol + 4] = u1;
        }
        if (r + 1 < NRND) {
            const size_t go = (size_t)(r + 1) * ROWS * rstr;
            ka = *(const float4*)(Kp + go);
            kb = *(const float4*)(Kp + go + 4);
            CP_WAIT(1);
        } else {
            CP_WAIT(0);
        }
        __syncthreads();

        const int buf = r & 1;
        #pragma unroll
        for (int kstp = 0; kstp < 4; kstp++) {
            const int sb = kstp * 8;
            const uint32_t a0 = __float_as_uint(Ks[sb + tig][d0 + gid]);
            const uint32_t a1 = __float_as_uint(Ks[sb + tig][d0 + gid + 8]);
            const uint32_t a2 = __float_as_uint(Ks[sb + tig + 4][d0 + gid]);
            const uint32_t a3 = __float_as_uint(Ks[sb + tig + 4][d0 + gid + 8]);
            #pragma unroll
            for (int nt = 0; nt < 4; nt++) {
                const int m = m0 + nt * 8 + gid;
                const uint32_t b0 = __float_as_uint(Vs[buf][sb + tig][m]);
                const uint32_t b1 = __float_as_uint(Vs[buf][sb + tig + 4][m]);
                mma8(acc[nt], a0, a1, a2, a3, b0, b1);
            }
        }
        __syncthreads();
    }

    float* dst = g_kv_part + ((size_t)split * NPAIR + pair) * DD * DD;
    const int dlo = d0 + gid;
    #pragma unroll
    for (int nt = 0; nt < 4; nt++) {
        const int m = m0 + nt * 8 + 2 * tig;
        *(float2*)(dst + dlo * DD + m)       = make_float2(acc[nt][0], acc[nt][1]);
        *(float2*)(dst + (dlo + 8) * DD + m) = make_float2(acc[nt][2], acc[nt][3]);
    }
    #pragma unroll
    for (int j = 0; j < 8; j++) {
        ks[j] += __shfl_xor_sync(0xffffffffu, ks[j], 8);
        ks[j] += __shfl_xor_sync(0xffffffffu, ks[j], 16);
    }
    if (lane < 8) {
        #pragma unroll
        for (int j = 0; j < 8; j++)
            atomicAdd(&ksum_s[lane * 8 + j], ks[j]);
    }
    __syncthreads();
    if (tid < DD)
        g_ksum_part[((size_t)split * NPAIR + pair) * DD + tid] = ksum_s[tid];
}

// ---------------- reduce partials ----------------
__global__ void reduce_kernel() {
    const int i = blockIdx.x * blockDim.x + threadIdx.x;
    if (i < NPAIR * DD * DD) {
        float s = 0.f;
        #pragma unroll
        for (int p = 0; p < SPL; p++) s += g_kv_part[(size_t)p * NPAIR * DD * DD + i];
        g_kv[i] = __uint_as_float(totf(s));
    } else {
        const int j = i - NPAIR * DD * DD;
        if (j < NPAIR * DD) {
            float s = 0.f;
            #pragma unroll
            for (int p = 0; p < SPL; p++) s += g_ksum_part[p * NPAIR * DD + j];
            g_ksum[j] = s;
        }
    }
}

// ---------------- kernel 2: output GEMM (persistent 4-tile, double-buffered) ---
// dynamic smem: qs[2][64][PADA] + kvs[64][PADB] + zs[2][64]  = 53760 B
#define K2_SMEM ((2 * TLQ * PADA + DD * PADB + 2 * TLQ) * 4)

__global__ __launch_bounds__(256, 4)
void out_kernel(const float* __restrict__ Q, float* __restrict__ O) {
    extern __shared__ float sm2[];
    float (*kvs)[PADB] = (float(*)[PADB])(sm2 + 2 * TLQ * PADA);
    float* zsb = sm2 + 2 * TLQ * PADA + DD * PADB;   // [2][TLQ]

    const int tid = threadIdx.x, warp = tid >> 5, lane = tid & 31;
    const int gid = lane >> 2, tig = lane & 3;
    const int pair = blockIdx.y, b = pair >> 3, hh = pair & 7;
    const int lbase = blockIdx.x * (TLQ * NT);

    // KV tile via cp.async, once per CTA
    {
        const float* kvp = g_kv + (size_t)pair * DD * DD;
        #pragma unroll
        for (int k = 0; k < 4; k++) {
            const int f = (k * 256 + tid) * 4;
            cp16(s2u(&kvs[f >> 6][f & 63]), kvp + f);
        }
        CP_COMMIT();
    }

    // per-thread q-prep mapping: 4 threads per row, 16 d each
    const int row = tid >> 2, qtr = tid & 3;
    const float* ksg = g_ksum + pair * DD + qtr * 16;
    float4 k4[4];
    #pragma unroll
    for (int i = 0; i < 4; i++) k4[i] = __ldg((const float4*)(ksg + i * 4));

    const float* qbase = Q + ((size_t)b * LL + lbase + row) * (NH * DD)
                           + (size_t)hh * DD + qtr * 16;
    float4 qv[4];
    #pragma unroll
    for (int i = 0; i < 4; i++) qv[i] = *(const float4*)(qbase + i * 4);

    const int lw = (warp & 3) * 16;
    const int m0 = (warp >> 2) * 32;

    #pragma unroll
    for (int t = 0; t < NT; t++) {
        const int buf = t & 1;
        float (*qs)[PADA] = (float(*)[PADA])(sm2 + buf * TLQ * PADA);
        float* zs = zsb + buf * TLQ;

        // phi + z-dot + tf32 STS (from prefetched registers)
        {
            float accz = 0.f;
            #pragma unroll
            for (int i = 0; i < 4; i++) {
                float4 q4 = qv[i];
                q4.x = phi(q4.x); q4.y = phi(q4.y); q4.z = phi(q4.z); q4.w = phi(q4.w);
                accz += q4.x * k4[i].x + q4.y * k4[i].y
                      + q4.z * k4[i].z + q4.w * k4[i].w;
                uint4 u;
                u.x = totf(q4.x); u.y = totf(q4.y); u.z = totf(q4.z); u.w = totf(q4.w);
                *(uint4*)&qs[row][qtr * 16 + i * 4] = u;
            }
            accz += __shfl_xor_sync(0xffffffffu, accz, 1);
            accz += __shfl_xor_sync(0xffffffffu, accz, 2);
            if (qtr == 0) zs[row] = 1.f / (accz + 1e-6f);
        }
        if (t == 0) CP_WAIT(0);
        __syncthreads();

        // prefetch Q(t+1) — overlaps MMA + store below
        if (t + 1 < NT) {
            const float* qn = qbase + (size_t)TLQ * (t + 1) * (NH * DD);
            #pragma unroll
            for (int i = 0; i < 4; i++) qv[i] = *(const float4*)(qn + i * 4);
        }

        // 16l x 32m per warp
        float acc[4][4];
        #pragma unroll
        for (int i = 0; i < 4; i++)
            #pragma unroll
            for (int j = 0; j < 4; j++) acc[i][j] = 0.f;

        #pragma unroll
        for (int kk = 0; kk < 8; kk++) {
            const int k0 = kk * 8;
            const uint32_t a0 = __float_as_uint(qs[lw + gid][k0 + tig]);
            const uint32_t a1 = __float_as_uint(qs[lw + gid + 8][k0 + tig]);
            const uint32_t a2 = __float_as_uint(qs[lw + gid][k0 + tig + 4]);
            const uint32_t a3 = __float_as_uint(qs[lw + gid + 8][k0 + tig + 4]);
            #pragma unroll
            for (int nt = 0; nt < 4; nt++) {
                const int m = m0 + nt * 8 + gid;
                const uint32_t b0 = __float_as_uint(kvs[k0 + tig][m]);
                const uint32_t b1 = __float_as_uint(kvs[k0 + tig + 4][m]);
                mma8(acc[nt], a0, a1, a2, a3, b0, b1);
            }
        }

        const float z0 = zs[lw + gid];
        const float z1 = zs[lw + gid + 8];
        float* dst = O + ((size_t)pair * LL + lbase + t * TLQ + lw + gid) * DD;
        #pragma unroll
        for (int nt = 0; nt < 4; nt++) {
            const int m = m0 + nt * 8 + 2 * tig;
            *(float2*)(dst + m)          = make_float2(acc[nt][0] * z0, acc[nt][1] * z0);
            *(float2*)(dst + 8 * DD + m) = make_float2(acc[nt][2] * z1, acc[nt][3] * z1);
        }
        // no trailing sync: next iter writes the other buffer
    }
}

// ---------------- launch ----------------
extern "C" void kernel_launch(void* const* d_in, const int* in_sizes, int n_in,
                              void* d_out, int out_size) {
    const float* Q = (const float*)d_in[0];
    const float* K = (const float*)d_in[1];
    const float* V = (const float*)d_in[2];
    float* O = (float*)d_out;

    cudaFuncSetAttribute(out_kernel, cudaFuncAttributeMaxDynamicSharedMemorySize, K2_SMEM);

    kv_kernel<<<dim3(SPL, NPAIR), 256>>>(K, V);
    reduce_kernel<<<(NPAIR * DD * DD + NPAIR * DD + 255) / 256, 256>>>();
    out_kernel<<<dim3(LL / (TLQ * NT), NPAIR), 256, K2_SMEM>>>(Q, O);
}